// round 16
// baseline (speedup 1.0000x reference)
#include <cuda_runtime.h>
#include <stdint.h>
#include <math.h>

#define N_ROLES 32768
#define IN_DIM  512
#define HID     512
#define N_EDGES 524288
#define N_LLMS  64

// ------------- output layout (float32 concat) -------------
#define OUT_IDX   0
#define OUT_LP    32768
#define OUT_EI    32769
#define OUT_EW    (32769 + 2*N_EDGES)

// ---------------- scratch (device globals) ----------------
__device__ float g_ew[N_EDGES];
__device__ float g_dinv[N_ROLES];
__device__ float g_xs[(size_t)N_ROLES * HID];    // x + cvec (UNscaled)
__device__ float g_rqe[(size_t)N_ROLES * HID];   // normalized rqe
__device__ float g_llmT[HID * N_LLMS];           // normalized llm, [dim][llm]
__device__ float g_cvec[HID];
__device__ int   g_cnt[N_ROLES];
__device__ int   g_ptr[N_ROLES + 1];
__device__ int   g_cur[N_ROLES];
__device__ int   g_perm[N_EDGES];
__device__ float g_lp[N_ROLES];
__device__ int   g_is64;

// ---------------- helpers ----------------
__device__ __forceinline__ int edge_val(const void* p, unsigned idx, int is64) {
    if (is64) return (int)((const long long*)p)[idx];
    return ((const int*)p)[idx];
}

// JAX threefry2x32, key = (0, 42)
__device__ __forceinline__ void threefry42(unsigned x0, unsigned x1, unsigned& o0, unsigned& o1) {
    const unsigned ks0 = 0u, ks1 = 42u, ks2 = 0x1BD11BDAu ^ 42u;
    x0 += ks0; x1 += ks1;
#define TFR(r) { x0 += x1; x1 = (x1 << (r)) | (x1 >> (32 - (r))); x1 ^= x0; }
    TFR(13) TFR(15) TFR(26) TFR(6)   x0 += ks1; x1 += ks2 + 1u;
    TFR(17) TFR(29) TFR(16) TFR(24)  x0 += ks2; x1 += ks0 + 2u;
    TFR(13) TFR(15) TFR(26) TFR(6)   x0 += ks0; x1 += ks1 + 3u;
    TFR(17) TFR(29) TFR(16) TFR(24)  x0 += ks1; x1 += ks2 + 4u;
    TFR(13) TFR(15) TFR(26) TFR(6)   x0 += ks2; x1 += ks0 + 5u;
#undef TFR
    o0 = x0; o1 = x1;
}

// jax_threefry_partitionable=True: bits[j] = o0 ^ o1 of threefry(key, (0, j))
__device__ __forceinline__ float gumbel_for(unsigned j) {
    unsigned o0, o1;
    threefry42(0u, j, o0, o1);
    unsigned bits = o0 ^ o1;
    float f = __uint_as_float((bits >> 9) | 0x3f800000u) - 1.0f;
    float u = (f > 0.f) ? f : 1.1754944e-38f;
    return -logf(-logf(u));
}

// split x into tf32 hi + tf32 lo (round-to-nearest tf32)
__device__ __forceinline__ void split_tf32(float x, float& hi, float& lo) {
    unsigned hb, lb;
    asm("cvt.rna.tf32.f32 %0, %1;" : "=r"(hb) : "f"(x));
    float hf = __uint_as_float(hb);
    float lf = x - hf;
    asm("cvt.rna.tf32.f32 %0, %1;" : "=r"(lb) : "f"(lf));
    hi = hf; lo = __uint_as_float(lb);
}

__device__ __forceinline__ void mma_tf32(float* c, const unsigned* a, const unsigned* b) {
    asm("mma.sync.aligned.m16n8k8.row.col.f32.tf32.tf32.f32 "
        "{%0,%1,%2,%3}, {%4,%5,%6,%7}, {%8,%9}, {%0,%1,%2,%3};"
        : "+f"(c[0]), "+f"(c[1]), "+f"(c[2]), "+f"(c[3])
        : "r"(a[0]), "r"(a[1]), "r"(a[2]), "r"(a[3]), "r"(b[0]), "r"(b[1]));
}

// ---------------- kernels ----------------

// fused: edge-dtype detect (block 0) + counter init (all blocks)
__global__ void k_detectinit(const unsigned* __restrict__ ei) {
    int i = blockIdx.x * blockDim.x + threadIdx.x;
    if (i < N_ROLES) { g_cnt[i] = 0; g_cur[i] = 0; }
    if (blockIdx.x == 0) {
        __shared__ int nz;
        if (threadIdx.x == 0) nz = 0;
        __syncthreads();
        int found = 0;
        for (int j = threadIdx.x; j < 2048; j += blockDim.x)
            if (ei[2 * j + 1] != 0u) found = 1;
        if (found) atomicExch(&nz, 1);
        __syncthreads();
        if (threadIdx.x == 0) g_is64 = (nz == 0);
    }
}

// ew = relu(edge_emb @ W_ew^T + b), fused with degree count.
// one warp per edge; lane 0 writes ew and bumps g_cnt[col].
__global__ void k_ew(const float* __restrict__ ee, const float* __restrict__ wew,
                     const float* __restrict__ bew, const void* __restrict__ ei,
                     float* __restrict__ out_ew) {
    int w = (blockIdx.x * blockDim.x + threadIdx.x) >> 5;
    int lane = threadIdx.x & 31;
    if (w >= N_EDGES) return;
    const float4* row = (const float4*)(ee + (size_t)w * IN_DIM);
    const float4* wv  = (const float4*)wew;
    float acc = 0.f;
#pragma unroll
    for (int j = 0; j < 4; j++) {
        float4 a = __ldg(&row[lane + 32 * j]);
        float4 b = __ldg(&wv[lane + 32 * j]);
        acc += a.x * b.x + a.y * b.y + a.z * b.z + a.w * b.w;
    }
#pragma unroll
    for (int off = 16; off; off >>= 1) acc += __shfl_down_sync(0xffffffffu, acc, off);
    if (lane == 0) {
        float r = fmaxf(acc + bew[0], 0.f);
        g_ew[w] = r;
        out_ew[w] = r;
        int col = edge_val(ei, (unsigned)(N_EDGES + w), g_is64);
        atomicAdd(&g_cnt[col], 1);
    }
}

__global__ void k_scan() {   // exclusive scan of g_cnt -> g_ptr, 1 block / 1024 thr
    __shared__ int sh[1024];
    int t = threadIdx.x;
    int base = t * 32;
    int loc[32]; int s = 0;
#pragma unroll
    for (int i = 0; i < 32; i++) { loc[i] = g_cnt[base + i]; s += loc[i]; }
    sh[t] = s; __syncthreads();
    for (int off = 1; off < 1024; off <<= 1) {
        int v = (t >= off) ? sh[t - off] : 0;
        __syncthreads();
        sh[t] += v;
        __syncthreads();
    }
    int run = (t ? sh[t - 1] : 0);
#pragma unroll
    for (int i = 0; i < 32; i++) { g_ptr[base + i] = run; run += loc[i]; }
    if (t == 1023) g_ptr[N_ROLES] = run;
}

__global__ void k_fill(const void* __restrict__ ei) {
    int e = blockIdx.x * blockDim.x + threadIdx.x;
    if (e >= N_EDGES) return;
    int col = edge_val(ei, (unsigned)(N_EDGES + e), g_is64);
    int p = atomicAdd(&g_cur[col], 1);
    g_perm[g_ptr[col] + p] = e;
}

// warp-per-node: bitonic sort edge ids (d<=32) + deterministic deg/dinv
__global__ void k_sortdeg() {
    int warp = (blockIdx.x * blockDim.x + threadIdx.x) >> 5;
    int lane = threadIdx.x & 31;
    if (warp >= N_ROLES) return;
    int n = warp;
    int s = g_ptr[n], e = g_ptr[n + 1];
    int d = e - s;
    if (d <= 32) {
        int v = (lane < d) ? g_perm[s + lane] : 0x7fffffff;
#pragma unroll
        for (int k = 2; k <= 32; k <<= 1)
#pragma unroll
            for (int j = k >> 1; j > 0; j >>= 1) {
                int o = __shfl_xor_sync(0xffffffffu, v, j);
                bool dirUp = ((lane & k) == 0);
                bool takeMax = (((lane & j) != 0) == dirUp);
                v = takeMax ? max(v, o) : min(v, o);
            }
        if (lane < d) g_perm[s + lane] = v;
        float w = (lane < d) ? g_ew[v] : 0.f;
#pragma unroll
        for (int off = 16; off; off >>= 1) w += __shfl_down_sync(0xffffffffu, w, off);
        if (lane == 0) g_dinv[n] = rsqrtf(1.0f + w);
    } else if (lane == 0) {
        for (int i = s + 1; i < e; i++) {
            int v = g_perm[i]; int j = i - 1;
            while (j >= s && g_perm[j] > v) { g_perm[j + 1] = g_perm[j]; j--; }
            g_perm[j + 1] = v;
        }
        float deg = 1.0f;
        for (int i = s; i < e; i++) deg += g_ew[g_perm[i]];
        g_dinv[n] = rsqrtf(deg);
    }
}

// llm raw encode -> g_llmT[o][r] (pre-norm)
__global__ void k_llm1(const float* __restrict__ emb, const float* __restrict__ W,
                       const float* __restrict__ b) {
    __shared__ float es[IN_DIM];
    int r = blockIdx.x, t = threadIdx.x;   // 256 threads
    for (int i = t; i < IN_DIM; i += 256) es[i] = emb[(size_t)r * IN_DIM + i];
    __syncthreads();
    float a0 = 0.f, a1 = 0.f;
    const float* w0 = W + (size_t)t * IN_DIM;
    const float* w1 = W + (size_t)(t + 256) * IN_DIM;
    for (int k = 0; k < IN_DIM; k++) { float ev = es[k]; a0 += ev * w0[k]; a1 += ev * w1[k]; }
    g_llmT[t * N_LLMS + r]         = a0 + b[t];
    g_llmT[(t + 256) * N_LLMS + r] = a1 + b[t + 256];
}

__global__ void k_llm2() {   // 1 block, 512 threads
    __shared__ float sinv[N_LLMS];
    int t = threadIdx.x;
    if (t < N_LLMS) {
        float ss = 0.f;
        for (int o = 0; o < HID; o++) { float v = g_llmT[o * N_LLMS + t]; ss += v * v; }
        sinv[t] = 1.0f / fmaxf(sqrtf(ss), 1e-12f);
    }
    __syncthreads();
    for (int i = t; i < HID * N_LLMS; i += 512) g_llmT[i] *= sinv[i & (N_LLMS - 1)];
}

// cvec[o] = q . W_gcn[o][512:1024]
__global__ void k_cvec(const float* __restrict__ q, const float* __restrict__ Wg) {
    __shared__ float qs[IN_DIM];
    int t = threadIdx.x;  // 256, 8 warps; grid 64
    for (int i = t; i < IN_DIM; i += 256) qs[i] = q[i];
    __syncthreads();
    int o = blockIdx.x * 8 + (t >> 5);
    int lane = t & 31;
    const float* wr = Wg + (size_t)o * (2 * IN_DIM) + IN_DIM;
    float acc = 0.f;
    for (int k = lane; k < IN_DIM; k += 32) acc += qs[k] * wr[k];
#pragma unroll
    for (int off = 16; off; off >>= 1) acc += __shfl_down_sync(0xffffffffu, acc, off);
    if (lane == 0) g_cvec[o] = acc;
}

// xs[n][o] = role[n] . Wg[o][:512] + cvec[o]   (dinv applied in k_agg)
// 3xTF32 TC GEMM (R11/R15 config, pinned at 2 CTA/SM)
#define BM 128
#define BN 128
__global__ void __launch_bounds__(256, 2)
k_gemm_tc(const float* __restrict__ role, const float* __restrict__ Wg) {
    __shared__ float As[2][128][16];
    __shared__ float Bs[2][128][16];
    __shared__ float cv[BN];
    int tid = threadIdx.x;
    int m0 = blockIdx.x * BM, n0 = blockIdx.y * BN;
    if (tid < BN) cv[tid] = g_cvec[n0 + tid];
    int warp = tid >> 5, lane = tid & 31;
    int wm = (warp & 1) * 64;
    int wn = (warp >> 1) * 32;
    int row = lane >> 2, col = lane & 3;

    int srow = tid & 127;
    bool isA = tid < 128;
    const float* src = isA ? (role + (size_t)(m0 + srow) * IN_DIM)
                           : (Wg + (size_t)(n0 + srow) * (2 * IN_DIM));
    int ssw = (srow >> 1) & 3;

    float4 v1 = *(const float4*)(src);
    float4 v2 = *(const float4*)(src + 4);

    {
        float* dst = isA ? &As[0][srow][0] : &Bs[0][srow][0];
        float e0[4] = {v1.x, v1.y, v1.z, v1.w};
        float e1[4] = {v2.x, v2.y, v2.z, v2.w};
#pragma unroll
        for (int j = 0; j < 4; j++) {
            float h0, l0, h1, l1;
            split_tf32(e0[j], h0, l0);
            split_tf32(e1[j], h1, l1);
            *(float4*)(dst + 4 * (j ^ ssw)) = make_float4(h0, l0, h1, l1);
        }
    }
    __syncthreads();

    float acc[4][4][4] = {};
    const int NITER = IN_DIM / 8;   // 64
    for (int k = 0; k < NITER; k++) {
        int cur = k & 1;
        if (k < NITER - 1) {
            v1 = *(const float4*)(src + (k + 1) * 8);
            v2 = *(const float4*)(src + (k + 1) * 8 + 4);
        }

        float4 af[4][2];
#pragma unroll
        for (int mt = 0; mt < 4; mt++) {
            int mA = wm + mt * 16 + row;
            af[mt][0] = *(const float4*)(&As[cur][mA][0]     + 4 * (col ^ ((mA >> 1) & 3)));
            af[mt][1] = *(const float4*)(&As[cur][mA + 8][0] + 4 * (col ^ (((mA + 8) >> 1) & 3)));
        }
        float4 bf[4];
#pragma unroll
        for (int nt = 0; nt < 4; nt++) {
            int nB = wn + nt * 8 + row;
            bf[nt] = *(const float4*)(&Bs[cur][nB][0] + 4 * (col ^ ((nB >> 1) & 3)));
        }

#pragma unroll
        for (int mt = 0; mt < 4; mt++) {
            unsigned ah[4] = {__float_as_uint(af[mt][0].x), __float_as_uint(af[mt][1].x),
                              __float_as_uint(af[mt][0].z), __float_as_uint(af[mt][1].z)};
            unsigned al[4] = {__float_as_uint(af[mt][0].y), __float_as_uint(af[mt][1].y),
                              __float_as_uint(af[mt][0].w), __float_as_uint(af[mt][1].w)};
#pragma unroll
            for (int nt = 0; nt < 4; nt++) {
                unsigned bh[2] = {__float_as_uint(bf[nt].x), __float_as_uint(bf[nt].z)};
                unsigned bl[2] = {__float_as_uint(bf[nt].y), __float_as_uint(bf[nt].w)};
                mma_tf32(acc[mt][nt], ah, bh);
                mma_tf32(acc[mt][nt], ah, bl);
                mma_tf32(acc[mt][nt], al, bh);
            }
        }

        if (k < NITER - 1) {
            int nxt = cur ^ 1;
            float* dst = isA ? &As[nxt][srow][0] : &Bs[nxt][srow][0];
            float e0[4] = {v1.x, v1.y, v1.z, v1.w};
            float e1[4] = {v2.x, v2.y, v2.z, v2.w};
#pragma unroll
            for (int j = 0; j < 4; j++) {
                float h0, l0, h1, l1;
                split_tf32(e0[j], h0, l0);
                split_tf32(e1[j], h1, l1);
                *(float4*)(dst + 4 * (j ^ ssw)) = make_float4(h0, l0, h1, l1);
            }
        }
        __syncthreads();
    }

#pragma unroll
    for (int mt = 0; mt < 4; mt++) {
        int m = m0 + wm + mt * 16 + row;
#pragma unroll
        for (int nt = 0; nt < 4; nt++) {
            int nc = wn + nt * 8 + col * 2;
            int n = n0 + nc;
            float c0 = acc[mt][nt][0] + cv[nc];
            float c1 = acc[mt][nt][1] + cv[nc + 1];
            float c2 = acc[mt][nt][2] + cv[nc];
            float c3 = acc[mt][nt][3] + cv[nc + 1];
            *(float2*)(g_xs + (size_t)m * HID + n)       = make_float2(c0, c1);
            *(float2*)(g_xs + (size_t)(m + 8) * HID + n) = make_float2(c2, c3);
        }
    }
}

// per-node CSR gather + bias + L2 norm -> g_rqe
// agg[c] = dinv_c * ( sum_e dinv_row*ew_e*x[row_e] + dinv_c*x[c] )
#define MAXD 96
__global__ void k_agg(const void* __restrict__ ei, const float* __restrict__ bgcn) {
    __shared__ int   s_row[MAXD];
    __shared__ float s_w[MAXD];
    __shared__ float red[128];
    int c = blockIdx.x;
    int t = threadIdx.x;                   // 128
    int is64 = g_is64;
    int s = g_ptr[c], e = g_ptr[c + 1];
    int d = e - s;
    int dl = d < MAXD ? d : MAXD;
    for (int i = t; i < dl; i += 128) {
        int ed = g_perm[s + i];
        int r  = edge_val(ei, (unsigned)ed, is64);
        s_row[i] = r;
        s_w[i]   = g_ew[ed] * g_dinv[r];
    }
    __syncthreads();
    float dvc = g_dinv[c];
    float4 acc = ((const float4*)g_xs)[(size_t)c * 128 + t];   // self loop
    acc.x *= dvc; acc.y *= dvc; acc.z *= dvc; acc.w *= dvc;
    for (int i = 0; i < dl; i++) {
        float w = s_w[i];
        float4 v = ((const float4*)g_xs)[(size_t)s_row[i] * 128 + t];
        acc.x += w * v.x; acc.y += w * v.y; acc.z += w * v.z; acc.w += w * v.w;
    }
    for (int i = MAXD; i < d; i++) {
        int ed = g_perm[s + i];
        int r = edge_val(ei, (unsigned)ed, is64);
        float w = g_ew[ed] * g_dinv[r];
        float4 v = ((const float4*)g_xs)[(size_t)r * 128 + t];
        acc.x += w * v.x; acc.y += w * v.y; acc.z += w * v.z; acc.w += w * v.w;
    }
    float4 b = ((const float4*)bgcn)[t];
    float4 pre;
    pre.x = dvc * acc.x + b.x; pre.y = dvc * acc.y + b.y;
    pre.z = dvc * acc.z + b.z; pre.w = dvc * acc.w + b.w;
    red[t] = pre.x * pre.x + pre.y * pre.y + pre.z * pre.z + pre.w * pre.w;
    __syncthreads();
    for (int o = 64; o; o >>= 1) { if (t < o) red[t] += red[t + o]; __syncthreads(); }
    float inv = 1.0f / fmaxf(sqrtf(red[0]), 1e-12f);
    float4 outv;
    outv.x = pre.x * inv; outv.y = pre.y * inv; outv.z = pre.z * inv; outv.w = pre.w * inv;
    ((float4*)g_rqe)[(size_t)c * 128 + t] = outv;
}

// 64 rows x 64 llms per block: GEMM + softmax + gumbel sample + logp
__global__ void k_score(float* __restrict__ out) {
    __shared__ float As[32][68];
    __shared__ float Bs[32][64];
    __shared__ float zs[64][65];
    int tid = threadIdx.x;                 // 256
    int tx = tid & 15, ty = tid >> 4;
    int r0 = blockIdx.x * 64;
    float acc[4][4] = {};
    int lr = tid >> 2;                     // 0..63
    int kq = (tid & 3) * 8;                // 0,8,16,24
    for (int k0 = 0; k0 < HID; k0 += 32) {
        float4 v1 = *(const float4*)(g_rqe + (size_t)(r0 + lr) * HID + k0 + kq);
        float4 v2 = *(const float4*)(g_rqe + (size_t)(r0 + lr) * HID + k0 + kq + 4);
        As[kq + 0][lr] = v1.x; As[kq + 1][lr] = v1.y; As[kq + 2][lr] = v1.z; As[kq + 3][lr] = v1.w;
        As[kq + 4][lr] = v2.x; As[kq + 5][lr] = v2.y; As[kq + 6][lr] = v2.z; As[kq + 7][lr] = v2.w;
        ((float4*)Bs)[tid]       = ((const float4*)(g_llmT + k0 * N_LLMS))[tid];
        ((float4*)Bs)[tid + 256] = ((const float4*)(g_llmT + k0 * N_LLMS))[tid + 256];
        __syncthreads();
#pragma unroll
        for (int kk = 0; kk < 32; kk++) {
            float4 a = *(const float4*)&As[kk][ty * 4];
            float4 b = *(const float4*)&Bs[kk][tx * 4];
            acc[0][0] += a.x * b.x; acc[0][1] += a.x * b.y; acc[0][2] += a.x * b.z; acc[0][3] += a.x * b.w;
            acc[1][0] += a.y * b.x; acc[1][1] += a.y * b.y; acc[1][2] += a.y * b.z; acc[1][3] += a.y * b.w;
            acc[2][0] += a.z * b.x; acc[2][1] += a.z * b.y; acc[2][2] += a.z * b.z; acc[2][3] += a.z * b.w;
            acc[3][0] += a.w * b.x; acc[3][1] += a.w * b.y; acc[3][2] += a.w * b.z; acc[3][3] += a.w * b.w;
        }
        __syncthreads();
    }
#pragma unroll
    for (int i = 0; i < 4; i++)
#pragma unroll
        for (int j = 0; j < 4; j++) zs[ty * 4 + i][tx * 4 + j] = acc[i][j];
    __syncthreads();

    int row = tid >> 2, s = tid & 3;       // quad per row
    int mlo = s * 16;
    float mx = -3.402823e38f;
    for (int m = mlo; m < mlo + 16; m++) mx = fmaxf(mx, zs[row][m]);
#pragma unroll
    for (int o = 1; o <= 2; o <<= 1) mx = fmaxf(mx, __shfl_xor_sync(0xffffffffu, mx, o));
    // cache exp(z - mx) once; reused bitwise-identically below
    float ex[16];
    float sum = 0.f;
#pragma unroll
    for (int m = 0; m < 16; m++) { ex[m] = expf(zs[row][mlo + m] - mx); sum += ex[m]; }
#pragma unroll
    for (int o = 1; o <= 2; o <<= 1) sum += __shfl_xor_sync(0xffffffffu, sum, o);

    float bv = -3.402823e38f; int bi = 64;
#pragma unroll
    for (int m = 0; m < 16; m++) {
        float sc = ex[m] / sum;
        float g = gumbel_for((unsigned)((r0 + row) * N_LLMS + mlo + m));
        float l = logf(sc) + g;
        if (l > bv) { bv = l; bi = mlo + m; }
    }
#pragma unroll
    for (int o = 1; o <= 2; o <<= 1) {
        float ov = __shfl_xor_sync(0xffffffffu, bv, o);
        int   oi = __shfl_xor_sync(0xffffffffu, bi, o);
        if (ov > bv || (ov == bv && oi < bi)) { bv = ov; bi = oi; }
    }
    if (s == 0) {
        float sc = expf(zs[row][bi] - mx) / sum;
        out[OUT_IDX + r0 + row] = (float)bi;
        g_lp[r0 + row] = logf(sc + 1e-5f);
    }
}

__global__ void k_lpsum(float* __restrict__ out) {   // 1 block, 1024 thr, tree sum
    __shared__ float sh[1024];
    int t = threadIdx.x;
    float sm = 0.f;
#pragma unroll
    for (int i = 0; i < 32; i++) sm += g_lp[t * 32 + i];
    sh[t] = sm; __syncthreads();
    for (int o = 512; o; o >>= 1) { if (t < o) sh[t] += sh[t + o]; __syncthreads(); }
    if (t == 0) out[OUT_LP] = sh[0];
}

__global__ void k_copyei(const void* __restrict__ ei, float* __restrict__ out) {
    int i = blockIdx.x * blockDim.x + threadIdx.x;
    if (i >= 2 * N_EDGES) return;
    out[OUT_EI + i] = (float)edge_val(ei, (unsigned)i, g_is64);
}

// ---------------- launch (k_ew is launch #3 = ncu target this round) --------
extern "C" void kernel_launch(void* const* d_in, const int* in_sizes, int n_in,
                              void* d_out, int out_size) {
    const float* q    = (const float*)d_in[0];
    const float* role = (const float*)d_in[1];
    const void*  ei   = d_in[2];
    const float* ee   = (const float*)d_in[3];
    const float* lemb = (const float*)d_in[4];
    const float* Wllm = (const float*)d_in[5];
    const float* bllm = (const float*)d_in[6];
    const float* Wew  = (const float*)d_in[7];
    const float* bew  = (const float*)d_in[8];
    const float* Wgcn = (const float*)d_in[9];
    const float* bgcn = (const float*)d_in[10];
    float* out = (float*)d_out;

    k_detectinit<<<(N_ROLES + 255) / 256, 256>>>((const unsigned*)ei);  // 0
    k_cvec<<<64, 256>>>(q, Wgcn);                                       // 1
    k_llm1<<<N_LLMS, 256>>>(lemb, Wllm, bllm);                          // 2
    k_ew<<<(N_EDGES * 32 + 255) / 256, 256>>>(ee, Wew, bew, ei, out + OUT_EW); // 3 <- ncu
    dim3 gg(N_ROLES / BM, HID / BN);
    k_gemm_tc<<<gg, 256>>>(role, Wgcn);
    k_scan<<<1, 1024>>>();
    k_fill<<<(N_EDGES + 255) / 256, 256>>>(ei);
    k_sortdeg<<<(N_ROLES * 32 + 255) / 256, 256>>>();
    k_llm2<<<1, 512>>>();
    k_agg<<<N_ROLES, 128>>>(ei, bgcn);
    k_score<<<N_ROLES / 64, 256>>>(out);
    k_lpsum<<<1, 1024>>>(out);
    k_copyei<<<(2 * N_EDGES + 255) / 256, 256>>>(ei, out);
}